// round 5
// baseline (speedup 1.0000x reference)
#include <cuda_runtime.h>

// Multi-scale SSIM quadtree loss, N=256, levels d=8..0.
// Level d: block side h=256>>d, mu = block_sum/h (faithful reference bug),
// weight W[d] = K_LOSS[d]*0.25^d, K_LOSS={9,8,7,6,5,4,3,2,1}.
//
// 16 CTAs x 1024 threads. CTA = 64x64 tile; 32 warps as 8x4 grid of 8x16
// blocks; lane = 1x4 strip (float4 loads). Warp does d=8..5 in registers;
// warp 0 folds the 32 warp sums (d=4..2) after producers bar.arrive+retire;
// ticket -> last CTA's warp 0 does the 4x4 tile grid (d=1..0). All terms
// use weight/replication (exact pow2).

#define SSIM_C1 0.2f

__device__ float4 g_tile[16];          // (Sx, Sy, partial, 0) per 64x64 tile
__device__ unsigned int g_count = 0;

// Weights pre-divided by replication factor (all exact in fp32):
#define W8_1  1.52587890625e-05f   // 1/65536          d=8
#define W7_2  6.103515625e-05f     // (2/16384)/2      d=7 rep2
#define W6_4  1.8310546875e-04f    // (3/4096)/4       d=6 rep4
#define W5_16 2.44140625e-04f      // (4/1024)/16      d=5 rep16
#define W4_2  0.009765625f         // (5/256)/2        d=4 rep2
#define W3_8  0.01171875f          // (6/64)/8         d=3 rep8
#define W2_32 0.013671875f         // (7/16)/32        d=2 rep32
#define W1_4  0.5f                 // (8/4)/4          d=1 rep4
#define W0_16 0.5625f              // 9/16             d=0 rep16

__device__ __forceinline__ float loss_term(float sx, float sy, float invh) {
    float mx = sx * invh;
    float my = sy * invh;
    return 1.0f - (2.0f * mx * my + SSIM_C1) / (mx * mx + my * my + SSIM_C1);
}

__device__ __forceinline__ float warp_sum(float v) {
    v += __shfl_xor_sync(0xffffffffu, v, 16);
    v += __shfl_xor_sync(0xffffffffu, v, 8);
    v += __shfl_xor_sync(0xffffffffu, v, 4);
    v += __shfl_xor_sync(0xffffffffu, v, 2);
    v += __shfl_xor_sync(0xffffffffu, v, 1);
    return v;
}

__global__ void __launch_bounds__(1024) Loss_13967233646850_kernel(
    const float* __restrict__ x, const float* __restrict__ y,
    float* __restrict__ out)
{
    __shared__ float sSx[32], sSy[32], sAcc[32];

    const int tid  = threadIdx.x;
    const int lane = tid & 31;
    const int w    = tid >> 5;          // 32 warps: 8x4 grid of 8x16 blocks
    const int b    = blockIdx.x;        // 16 CTAs: 4x4 grid of 64x64 tiles

    // ---- Phase A (per warp): d=8..5 over this warp's 8x16 pixel block ----
    {
        const int row = (b >> 2) * 64 + (w >> 2) * 8 + (lane >> 2);
        const int col = (b & 3)  * 64 + (w & 3) * 16 + (lane & 3) * 4;
        const int idx = row * 256 + col;

        const float4 px = *(const float4*)(x + idx);
        const float4 py = *(const float4*)(y + idx);

        // d=8: per pixel
        float acc = W8_1 * (loss_term(px.x, py.x, 1.0f) + loss_term(px.y, py.y, 1.0f) +
                            loss_term(px.z, py.z, 1.0f) + loss_term(px.w, py.w, 1.0f));

        // 1x2 sums within the strip
        float sabx = px.x + px.y, scdx = px.z + px.w;
        float saby = py.x + py.y, scdy = py.z + py.w;

        // d=7: 2x2 (vertical pair via xor4); two per lane, rep2 each
        float s2Lx = sabx + __shfl_xor_sync(0xffffffffu, sabx, 4);
        float s2Ly = saby + __shfl_xor_sync(0xffffffffu, saby, 4);
        float s2Rx = scdx + __shfl_xor_sync(0xffffffffu, scdx, 4);
        float s2Ry = scdy + __shfl_xor_sync(0xffffffffu, scdy, 4);
        acc += W7_2 * (loss_term(s2Lx, s2Ly, 0.5f) + loss_term(s2Rx, s2Ry, 0.5f));

        // d=6: 4x4 (rows via xor8, cols = full strip), rep4
        float s4x = s2Lx + s2Rx, s4y = s2Ly + s2Ry;
        s4x += __shfl_xor_sync(0xffffffffu, s4x, 8);
        s4y += __shfl_xor_sync(0xffffffffu, s4y, 8);
        acc += W6_4 * loss_term(s4x, s4y, 0.25f);

        // d=5: 8x8 (rows via xor16, col quads via xor1), rep16
        float s8x = s4x + __shfl_xor_sync(0xffffffffu, s4x, 16);
        float s8y = s4y + __shfl_xor_sync(0xffffffffu, s4y, 16);
        s8x += __shfl_xor_sync(0xffffffffu, s8x, 1);
        s8y += __shfl_xor_sync(0xffffffffu, s8y, 1);
        acc += W5_16 * loss_term(s8x, s8y, 0.125f);

        // warp total 8x16 (col quads via xor2)
        float swx = s8x + __shfl_xor_sync(0xffffffffu, s8x, 2);
        float swy = s8y + __shfl_xor_sync(0xffffffffu, s8y, 2);

        acc = warp_sum(acc);
        if (lane == 0) { sSx[w] = swx; sSy[w] = swy; sAcc[w] = acc; }
    }

    // Producers signal and retire; warp 0 waits for all 32 warps.
    if (w != 0) {
        asm volatile("bar.arrive 1, 1024;" ::: "memory");
        return;
    }
    asm volatile("bar.sync 1, 1024;" ::: "memory");

    // ---- Warp 0: fold 32 warp blocks (d=4..2), write tile, ticket ----
    unsigned int ticket;
    {
        // lane = warp index: wr = lane>>2 (8 rows), wc = lane&3 (4 cols);
        // warp block is 8x16 pixels.
        float sx  = sSx[lane];
        float sy  = sSy[lane];
        float acc = sAcc[lane];

        // d=4: 16x16 = 2 warp-rows (wr bit0 -> xor4), rep2
        float s16x = sx + __shfl_xor_sync(0xffffffffu, sx, 4);
        float s16y = sy + __shfl_xor_sync(0xffffffffu, sy, 4);
        acc += W4_2 * loss_term(s16x, s16y, 1.0f / 16.0f);

        // d=3: 32x32 = 4 warp-rows x 2 warp-cols (wr bit1 -> xor8, wc bit0 -> xor1), rep8
        float s32x = s16x + __shfl_xor_sync(0xffffffffu, s16x, 8);
        float s32y = s16y + __shfl_xor_sync(0xffffffffu, s16y, 8);
        s32x += __shfl_xor_sync(0xffffffffu, s32x, 1);
        s32y += __shfl_xor_sync(0xffffffffu, s32y, 1);
        acc += W3_8 * loss_term(s32x, s32y, 1.0f / 32.0f);

        // d=2: 64x64 = full CTA (wr bit2 -> xor16, wc bit1 -> xor2), rep32
        float s64x = s32x + __shfl_xor_sync(0xffffffffu, s32x, 16);
        float s64y = s32y + __shfl_xor_sync(0xffffffffu, s32y, 16);
        s64x += __shfl_xor_sync(0xffffffffu, s64x, 2);
        s64y += __shfl_xor_sync(0xffffffffu, s64y, 2);
        acc += W2_32 * loss_term(s64x, s64y, 1.0f / 64.0f);

        acc = warp_sum(acc);
        if (lane == 0) {
            g_tile[b] = make_float4(s64x, s64y, acc, 0.0f);
            __threadfence();
            ticket = atomicAdd(&g_count, 1u);
        }
        ticket = __shfl_sync(0xffffffffu, ticket, 0);
    }
    if (ticket != gridDim.x - 1) return;

    // ---- Phase B (warp 0 of last CTA): 4x4 tile grid, d=1..0 ----
    __threadfence();
    {
        // lane<16: tile (tr = lane>>2, tc = lane&3); lanes 16..31 zero —
        // xor1/2/4/8 never cross bit4, and loss_term(0,0)==0.
        float4 t = (lane < 16) ? g_tile[lane] : make_float4(0.f, 0.f, 0.f, 0.f);
        float acc = t.z;

        // d=1: 128x128 = 2x2 tiles (tr bit0 -> xor4, tc bit0 -> xor1), rep4
        float sx = t.x + __shfl_xor_sync(0xffffffffu, t.x, 4);
        float sy = t.y + __shfl_xor_sync(0xffffffffu, t.y, 4);
        sx += __shfl_xor_sync(0xffffffffu, sx, 1);
        sy += __shfl_xor_sync(0xffffffffu, sy, 1);
        acc += W1_4 * loss_term(sx, sy, 1.0f / 128.0f);

        // d=0: full image (tr bit1 -> xor8, tc bit1 -> xor2), rep16
        float Sx = sx + __shfl_xor_sync(0xffffffffu, sx, 8);
        float Sy = sy + __shfl_xor_sync(0xffffffffu, sy, 8);
        Sx += __shfl_xor_sync(0xffffffffu, Sx, 2);
        Sy += __shfl_xor_sync(0xffffffffu, Sy, 2);
        acc += W0_16 * loss_term(Sx, Sy, 1.0f / 256.0f);

        acc = warp_sum(acc);
        if (lane == 0) {
            out[0] = acc;
            g_count = 0;   // reset for graph replay
        }
    }
}

extern "C" void kernel_launch(void* const* d_in, const int* in_sizes, int n_in,
                              void* d_out, int out_size) {
    const float* x = (const float*)d_in[0];
    const float* y = (const float*)d_in[1];
    float* out = (float*)d_out;
    Loss_13967233646850_kernel<<<16, 1024>>>(x, y, out);
}

// round 6
// speedup vs baseline: 1.3413x; 1.3413x over previous
#include <cuda_runtime.h>

// Multi-scale SSIM quadtree loss, N=256, levels d=8..0.
// Level d: block side h=256>>d, mu = block_sum/h (faithful reference bug),
// weight W[d] = K_LOSS[d]*0.25^d, K_LOSS={9,8,7,6,5,4,3,2,1}.
//
// Best-measured config (R2): 256 CTAs x 128 threads; warp = 8x8 pixel block,
// lane = 1x2 strip; warp-shuffle quadtrees with weight/replication (exact
// pow2). Micro-cuts: single acq_rel ticket atomic (no threadfences), float4
// tile record (1 STG.128), producers bar.arrive+retire.

#define SSIM_C1 0.2f

__device__ float4 g_tile[256];        // (Sx, Sy, partial, 0) per 16x16 tile
__device__ unsigned int g_count = 0;

// Weights pre-divided by lane replication (all exact in fp32):
#define W8_R 1.52587890625e-05f   // 1/65536          d=8 rep1
#define W7_R 6.103515625e-05f     // (2/16384)/2      d=7 rep2
#define W6_R 9.1552734375e-05f    // (3/4096)/8       d=6 rep8
#define W5_R 1.220703125e-04f     // (4/1024)/32      d=5 rep32
#define W4_F 0.01953125f          // 5/256            d=4 once
#define W3_R 0.046875f            // (6/64)/2         d=3 rep2
#define W2_R 0.0546875f           // (7/16)/8         d=2 rep8
#define W1_R 0.0625f              // (8/4)/32         d=1 rep32
#define W0_F 9.0f                 // 9                d=0 once

__device__ __forceinline__ float loss_term(float sx, float sy, float invh) {
    float mx = sx * invh;
    float my = sy * invh;
    return 1.0f - (2.0f * mx * my + SSIM_C1) / (mx * mx + my * my + SSIM_C1);
}

// Quadtree over an 8x8 grid of per-lane 1x2 sums (lane l -> row l>>2,
// colpair l&3). Adds 3 level terms, returns full 8x8-grid sums.
__device__ __forceinline__ void warp_quadtree(
    float s1x, float s1y, float& acc, float& s8x, float& s8y,
    float wA, float ihA, float wB, float ihB, float wC, float ihC)
{
    float s2x = s1x + __shfl_xor_sync(0xffffffffu, s1x, 4);
    float s2y = s1y + __shfl_xor_sync(0xffffffffu, s1y, 4);
    acc += wA * loss_term(s2x, s2y, ihA);
    float s4x = s2x + __shfl_xor_sync(0xffffffffu, s2x, 8);
    float s4y = s2y + __shfl_xor_sync(0xffffffffu, s2y, 8);
    s4x += __shfl_xor_sync(0xffffffffu, s4x, 1);
    s4y += __shfl_xor_sync(0xffffffffu, s4y, 1);
    acc += wB * loss_term(s4x, s4y, ihB);
    s8x = s4x + __shfl_xor_sync(0xffffffffu, s4x, 16);
    s8y = s4y + __shfl_xor_sync(0xffffffffu, s4y, 16);
    s8x += __shfl_xor_sync(0xffffffffu, s8x, 2);
    s8y += __shfl_xor_sync(0xffffffffu, s8y, 2);
    acc += wC * loss_term(s8x, s8y, ihC);
}

__device__ __forceinline__ float warp_sum(float v) {
    v += __shfl_xor_sync(0xffffffffu, v, 16);
    v += __shfl_xor_sync(0xffffffffu, v, 8);
    v += __shfl_xor_sync(0xffffffffu, v, 4);
    v += __shfl_xor_sync(0xffffffffu, v, 2);
    v += __shfl_xor_sync(0xffffffffu, v, 1);
    return v;
}

__global__ void __launch_bounds__(128) Loss_13967233646850_kernel(
    const float* __restrict__ x, const float* __restrict__ y,
    float* __restrict__ out)
{
    __shared__ float sSx[4], sSy[4], sAcc[4];
    __shared__ bool  isLast;

    const int tid  = threadIdx.x;
    const int lane = tid & 31;
    const int w    = tid >> 5;           // warp 0..3 -> quadrant of 16x16 tile
    const int b    = blockIdx.x;

    // ---- Phase A: d=8..5 over this warp's 8x8 pixel block ----
    {
        const int row = (b >> 4) * 16 + (w >> 1) * 8 + (lane >> 2);
        const int col = (b & 15) * 16 + (w & 1) * 8 + (lane & 3) * 2;
        const int idx = row * 256 + col;

        const float2 px = *(const float2*)(x + idx);
        const float2 py = *(const float2*)(y + idx);

        float acc = W8_R * (loss_term(px.x, py.x, 1.0f) +
                            loss_term(px.y, py.y, 1.0f));
        float s8x, s8y;
        warp_quadtree(px.x + px.y, py.x + py.y, acc, s8x, s8y,
                      W7_R, 0.5f, W6_R, 0.25f, W5_R, 0.125f);
        acc = warp_sum(acc);
        if (lane == 0) { sSx[w] = s8x; sSy[w] = s8y; sAcc[w] = acc; }
    }

    // Producers signal barrier 1 and wait only on barrier 2 (phase B gate).
    if (w != 0) {
        asm volatile("bar.arrive 1, 128;" ::: "memory");
    } else {
        asm volatile("bar.sync 1, 128;" ::: "memory");
        // ---- Warp 0 lane 0: d=4 term, tile record, acq_rel ticket ----
        if (lane == 0) {
            float Sx = sSx[0] + sSx[1] + sSx[2] + sSx[3];
            float Sy = sSy[0] + sSy[1] + sSy[2] + sSy[3];
            float a  = sAcc[0] + sAcc[1] + sAcc[2] + sAcc[3];
            a += W4_F * loss_term(Sx, Sy, 1.0f / 16.0f);   // d=4 (16x16 tile)
            g_tile[b] = make_float4(Sx, Sy, a, 0.0f);
            // Single acq_rel RMW: release orders the record store above,
            // acquire orders the last CTA's g_tile reads below.
            unsigned int t;
            asm volatile("atom.add.acq_rel.gpu.global.u32 %0, [%1], 1;"
                         : "=r"(t) : "l"(&g_count) : "memory");
            isLast = (t == 255u);
        }
    }
    __syncthreads();
    if (!isLast) return;

    // ---- Phase B: last CTA, 16x16 tile grid, d=3..0 ----
    {
        // Warp w owns an 8x8 quadrant of the tile grid; lane = 1x2 tile pair.
        const int trow = (w >> 1) * 8 + (lane >> 2);
        const int tcol = (w & 1) * 8 + (lane & 3) * 2;
        const int ti   = trow * 16 + tcol;

        const float4 t0 = g_tile[ti];
        const float4 t1 = g_tile[ti + 1];

        float acc = t0.z + t1.z;
        float s8x, s8y;
        warp_quadtree(t0.x + t1.x, t0.y + t1.y, acc, s8x, s8y,
                      W3_R, 1.0f / 32.0f, W2_R, 1.0f / 64.0f, W1_R, 1.0f / 128.0f);
        acc = warp_sum(acc);
        if (lane == 0) { sSx[w] = s8x; sSy[w] = s8y; sAcc[w] = acc; }
    }
    __syncthreads();

    if (tid == 0) {
        float Sx = sSx[0] + sSx[1] + sSx[2] + sSx[3];
        float Sy = sSy[0] + sSy[1] + sSy[2] + sSy[3];
        float a  = sAcc[0] + sAcc[1] + sAcc[2] + sAcc[3];
        a += W0_F * loss_term(Sx, Sy, 1.0f / 256.0f);   // d=0 (full image)
        out[0] = a;
        g_count = 0;                                    // reset for graph replay
    }
}

extern "C" void kernel_launch(void* const* d_in, const int* in_sizes, int n_in,
                              void* d_out, int out_size) {
    const float* x = (const float*)d_in[0];
    const float* y = (const float*)d_in[1];
    float* out = (float*)d_out;
    Loss_13967233646850_kernel<<<256, 128>>>(x, y, out);
}